// round 2
// baseline (speedup 1.0000x reference)
#include <cuda_runtime.h>

// Problem constants
#define Sx 512
#define Bx 64
#define Ex 512
#define Hx 768
#define G4x 3072
#define SBx 32768      // Sx*Bx
#define NCTA 144       // persistent grid (<=148 SMs -> all co-resident)
#define NTHR 36864     // NCTA*256

// ---------------- scratch (device globals: allocation-guard-safe) -------------
__device__ float g_emb[(size_t)SBx * Ex];    //  67 MB  gathered embeddings [SB,E]
__device__ float g_xf[(size_t)SBx * G4x];    // 402 MB  emb@Wi_f + bi_f     [SB,4H]
__device__ float g_gb[(size_t)SBx * G4x];    // 402 MB  emb@Wi_b + bi_b     [SB,4H]
__device__ float g_hsf[(size_t)SBx * Hx];    // 100 MB  forward hiddens     [S,B,H]
__device__ float g_hsb[(size_t)SBx * Hx];    // 100 MB  backward hiddens    [S,B,H]
__device__ float g_part[6 * Bx * G4x];       // 4.7 MB  split-K partials [6,B,4H]
__device__ float g_h[Bx * Hx];               // current hidden

// grid barrier state
__device__ unsigned int g_bar_count = 0;
__device__ volatile unsigned int g_bar_gen = 0;

// ---------------- f32x2 helpers (FFMA2 dual-issue path, PTX-only) -------------
__device__ __forceinline__ void fma2(unsigned long long& d, unsigned long long a,
                                     unsigned long long b) {
    asm("fma.rn.f32x2 %0, %1, %2, %0;" : "+l"(d) : "l"(a), "l"(b));
}
__device__ __forceinline__ unsigned long long pack2(float x) {
    unsigned long long r;
    asm("mov.b64 %0, {%1, %1};" : "=l"(r) : "f"(x));
    return r;
}
__device__ __forceinline__ float2 unpack2(unsigned long long v) {
    float2 f;
    asm("mov.b64 {%0, %1}, %2;" : "=f"(f.x), "=f"(f.y) : "l"(v));
    return f;
}

__device__ __forceinline__ float sigm(float x) { return 1.0f / (1.0f + expf(-x)); }

// grid-wide barrier (sense = monotonically increasing generation).
// Safe across graph replays: local gen is seeded from the global at kernel start.
__device__ __forceinline__ void gsync(unsigned int& gen) {
    __syncthreads();
    if (threadIdx.x == 0) {
        gen++;
        __threadfence();
        if (atomicAdd(&g_bar_count, 1) == NCTA - 1) {
            g_bar_count = 0;
            __threadfence();
            g_bar_gen = gen;
        } else {
            while (g_bar_gen != gen) { __nanosleep(32); }
        }
        __threadfence();
    }
    __syncthreads();
}

// ---------------- 1. embedding gather -----------------------------------------
__global__ void embed_kernel(const int* __restrict__ tokens,
                             const float* __restrict__ embedding) {
    int idx = blockIdx.x * blockDim.x + threadIdx.x;  // over SB * E/4
    int e4 = idx & (Ex / 4 - 1);
    int sb = idx >> 7;  // idx / (Ex/4)
    int tok = tokens[sb];
    float4 v = *(const float4*)(embedding + (size_t)tok * Ex + e4 * 4);
    *(float4*)(g_emb + (size_t)sb * Ex + e4 * 4) = v;
}

// ---------------- 2. big input GEMM: out = g_emb @ W + bias -------------------
// M=32768, K=512, N=3072. Tile 128x128x16, 256 thr, micro 8m x 8n (f32x2 pairs)
__global__ __launch_bounds__(256, 2)
void big_gemm_kernel(const float* __restrict__ W, const float* __restrict__ bias,
                     int dst) {
    __shared__ float As[16][128];
    __shared__ float Bs[16][128];
    float* out = dst ? g_gb : g_xf;
    const int t = threadIdx.x;
    const int mblk = blockIdx.x;  // 256
    const int nblk = blockIdx.y;  // 24
    const float* A = g_emb + (size_t)mblk * 128 * Ex;
    const float* Wb = W + nblk * 128;

    unsigned long long acc[8][4];
#pragma unroll
    for (int i = 0; i < 8; ++i)
#pragma unroll
        for (int j = 0; j < 4; ++j) acc[i][j] = 0ull;

    const int la_row = t >> 1;
    const int la_k = (t & 1) * 8;
    const int lb_k = t >> 5;
    const int lb_n = (t & 31) * 4;
    const int m0 = (t >> 4) * 8;
    const int n0 = (t & 15) * 8;

    for (int k0 = 0; k0 < Ex; k0 += 16) {
        float4 va0 = *(const float4*)(A + (size_t)la_row * Ex + k0 + la_k);
        float4 va1 = *(const float4*)(A + (size_t)la_row * Ex + k0 + la_k + 4);
        float4 vb0 = *(const float4*)(Wb + (size_t)(k0 + lb_k) * G4x + lb_n);
        float4 vb1 = *(const float4*)(Wb + (size_t)(k0 + lb_k + 8) * G4x + lb_n);
        As[la_k + 0][la_row] = va0.x; As[la_k + 1][la_row] = va0.y;
        As[la_k + 2][la_row] = va0.z; As[la_k + 3][la_row] = va0.w;
        As[la_k + 4][la_row] = va1.x; As[la_k + 5][la_row] = va1.y;
        As[la_k + 6][la_row] = va1.z; As[la_k + 7][la_row] = va1.w;
        *(float4*)(&Bs[lb_k][lb_n]) = vb0;
        *(float4*)(&Bs[lb_k + 8][lb_n]) = vb1;
        __syncthreads();
#pragma unroll
        for (int k = 0; k < 16; ++k) {
            float a[8];
            *(float4*)(a) = *(const float4*)(&As[k][m0]);
            *(float4*)(a + 4) = *(const float4*)(&As[k][m0 + 4]);
            ulonglong2 b01 = *(const ulonglong2*)(&Bs[k][n0]);
            ulonglong2 b23 = *(const ulonglong2*)(&Bs[k][n0 + 4]);
            unsigned long long bb0 = b01.x, bb1 = b01.y, bb2 = b23.x, bb3 = b23.y;
#pragma unroll
            for (int i = 0; i < 8; ++i) {
                unsigned long long a2 = pack2(a[i]);
                fma2(acc[i][0], a2, bb0);
                fma2(acc[i][1], a2, bb1);
                fma2(acc[i][2], a2, bb2);
                fma2(acc[i][3], a2, bb3);
            }
        }
        __syncthreads();
    }
#pragma unroll
    for (int i = 0; i < 8; ++i) {
        size_t gm = (size_t)mblk * 128 + m0 + i;
#pragma unroll
        for (int j = 0; j < 4; ++j) {
            int gn = nblk * 128 + n0 + j * 2;
            float2 v = unpack2(acc[i][j]);
            v.x += bias[gn];
            v.y += bias[gn + 1];
            *(float2*)(out + gm * G4x + gn) = v;
        }
    }
}

// ---------------- 3. persistent forward recurrence ------------------------------
// 144 CTAs: (nblk = bid%24) x (kc = bid/24). Per step:
//   partials: part[kc][b][n] = sum_{k in kc chunk} h[b][k] * Wh[k][n]
//   gsync; gates (c in registers, h -> g_h via stcg); gsync.
// Wh tile hoisted to smem once. h/part cross-SM traffic via ldcg/stcg (L1 bypass).
#define WS_STRIDE 132
#define HT_STRIDE 65
__global__ __launch_bounds__(256, 1)
void fwd_persistent(const float* __restrict__ Wh, const float* __restrict__ bh) {
    extern __shared__ float smem[];
    float* Ws = smem;                       // [128][WS_STRIDE]
    float* hsT = smem + 128 * WS_STRIDE;    // [128][HT_STRIDE] (k-major, b minor)

    const int t = threadIdx.x;
    const int bid = blockIdx.x;
    const int nblk = bid % 24;
    const int kc = bid / 24;
    unsigned int gen = g_bar_gen;  // stable between runs (read before any barrier)

    // zero h
    for (int i = bid * 256 + t; i < Bx * Hx; i += NTHR) __stcg(g_h + i, 0.0f);

    // hoist Wh tile [kc*128 .. +128) x [nblk*128 .. +128) into smem (once)
#pragma unroll
    for (int q = 0; q < 16; ++q) {
        int i = t + 256 * q;          // < 4096
        int k = i >> 5;
        int n4 = (i & 31) * 4;
        float4 v = *(const float4*)(Wh + (size_t)(kc * 128 + k) * G4x +
                                    nblk * 128 + n4);
        *(float4*)(&Ws[k * WS_STRIDE + n4]) = v;
    }

    // gates thread constants (each thread owns up to 2 gate elements, c in regs)
    const int gbase = bid * 256 + t;
    int gb_[2], gj_[2];
    float bhv[2][4];
    float c_reg[2] = {0.0f, 0.0f};
#pragma unroll
    for (int slot = 0; slot < 2; ++slot) {
        int idx = gbase + slot * NTHR;
        if (idx < Bx * Hx) {
            gb_[slot] = idx / Hx;
            gj_[slot] = idx - gb_[slot] * Hx;
#pragma unroll
            for (int gi = 0; gi < 4; ++gi) bhv[slot][gi] = bh[gj_[slot] + gi * Hx];
        } else {
            gb_[slot] = -1;
            gj_[slot] = 0;
        }
    }

    const int b0 = (t >> 4) * 4;
    const int n0 = (t & 15) * 8;

    gsync(gen);  // h zeroed, everyone ready

    for (int s = 0; s < Sx; ++s) {
        // ---- load h slice [64][128] into smem (transposed), L2-coherent ----
#pragma unroll
        for (int q = 0; q < 8; ++q) {
            int i = t + 256 * q;      // < 2048
            int b = i >> 5;
            int kq = (i & 31) * 4;
            float4 v = __ldcg((const float4*)(g_h + b * Hx + kc * 128 + kq));
            hsT[(kq + 0) * HT_STRIDE + b] = v.x;
            hsT[(kq + 1) * HT_STRIDE + b] = v.y;
            hsT[(kq + 2) * HT_STRIDE + b] = v.z;
            hsT[(kq + 3) * HT_STRIDE + b] = v.w;
        }
        __syncthreads();

        // ---- GEMM: 4b x 8n per thread over 128 k ----
        unsigned long long acc[4][4];
#pragma unroll
        for (int i = 0; i < 4; ++i)
#pragma unroll
            for (int j = 0; j < 4; ++j) acc[i][j] = 0ull;

#pragma unroll 4
        for (int k = 0; k < 128; ++k) {
            float a0 = hsT[k * HT_STRIDE + b0 + 0];
            float a1 = hsT[k * HT_STRIDE + b0 + 1];
            float a2 = hsT[k * HT_STRIDE + b0 + 2];
            float a3 = hsT[k * HT_STRIDE + b0 + 3];
            ulonglong2 w01 = *(const ulonglong2*)(&Ws[k * WS_STRIDE + n0]);
            ulonglong2 w23 = *(const ulonglong2*)(&Ws[k * WS_STRIDE + n0 + 4]);
            unsigned long long p0 = pack2(a0), p1 = pack2(a1), p2 = pack2(a2),
                               p3 = pack2(a3);
            fma2(acc[0][0], p0, w01.x); fma2(acc[0][1], p0, w01.y);
            fma2(acc[0][2], p0, w23.x); fma2(acc[0][3], p0, w23.y);
            fma2(acc[1][0], p1, w01.x); fma2(acc[1][1], p1, w01.y);
            fma2(acc[1][2], p1, w23.x); fma2(acc[1][3], p1, w23.y);
            fma2(acc[2][0], p2, w01.x); fma2(acc[2][1], p2, w01.y);
            fma2(acc[2][2], p2, w23.x); fma2(acc[2][3], p2, w23.y);
            fma2(acc[3][0], p3, w01.x); fma2(acc[3][1], p3, w01.y);
            fma2(acc[3][2], p3, w23.x); fma2(acc[3][3], p3, w23.y);
        }
        // epilogue -> partials (L2-coherent stores)
#pragma unroll
        for (int i = 0; i < 4; ++i) {
#pragma unroll
            for (int j = 0; j < 4; ++j) {
                float2 v = unpack2(acc[i][j]);
                int gn = nblk * 128 + n0 + j * 2;
                __stcg((float2*)(g_part + ((size_t)(kc * Bx + b0 + i)) * G4x + gn),
                       v);
            }
        }
        __syncthreads();  // hsT reuse guarded by gsync below anyway
        gsync(gen);

        // ---- gates ----
        const float* xfs = g_xf + (size_t)s * Bx * G4x;
#pragma unroll
        for (int slot = 0; slot < 2; ++slot) {
            if (gb_[slot] >= 0) {
                int b = gb_[slot], j = gj_[slot];
                const float* xf = xfs + (size_t)b * G4x + j;
                float g[4];
#pragma unroll
                for (int gi = 0; gi < 4; ++gi) {
                    float v = __ldcs(xf + gi * Hx) + bhv[slot][gi];
                    const float* pp = g_part + (size_t)b * G4x + j + gi * Hx;
#pragma unroll
                    for (int kcc = 0; kcc < 6; ++kcc)
                        v += __ldcg(pp + (size_t)kcc * (Bx * G4x));
                    g[gi] = v;
                }
                float c = c_reg[slot];
                float r = sigm(g[0]);
                float f = sigm(g[1]);
                float gg = tanhf(g[2]);
                float o = sigm(g[3]);
                c = f * c + r * gg;
                float h = o * tanhf(c);
                c_reg[slot] = c;
                int idx = b * Hx + j;
                __stcg(g_h + idx, h);
                g_hsf[(size_t)s * (Bx * Hx) + idx] = h;
            }
        }
        gsync(gen);
    }
}

// ---------------- 4. one-shot hidden GEMM for hT @ Wh_b (split-K partials) ----
__global__ __launch_bounds__(256, 2)
void step_gemm_kernel(const float* __restrict__ Wh) {
    __shared__ float hsT[16][68];
    __shared__ float Wsm[16][128];
    const int t = threadIdx.x;
    const int nblk = blockIdx.x;  // 24
    const int kc = blockIdx.y;    // 6
    const float* Wb = Wh + nblk * 128;

    unsigned long long acc[4][4];
#pragma unroll
    for (int i = 0; i < 4; ++i)
#pragma unroll
        for (int j = 0; j < 4; ++j) acc[i][j] = 0ull;

    const int la_b = t >> 2;
    const int la_k = (t & 3) * 4;
    const int lb_k = t >> 5;
    const int lb_n = (t & 31) * 4;
    const int b0 = (t >> 4) * 4;
    const int n0 = (t & 15) * 8;

    for (int kt = 0; kt < 8; ++kt) {
        int k0 = kc * 128 + kt * 16;
        float4 va = *(const float4*)(g_h + la_b * Hx + k0 + la_k);
        float4 vb0 = *(const float4*)(Wb + (size_t)(k0 + lb_k) * G4x + lb_n);
        float4 vb1 = *(const float4*)(Wb + (size_t)(k0 + lb_k + 8) * G4x + lb_n);
        hsT[la_k + 0][la_b] = va.x; hsT[la_k + 1][la_b] = va.y;
        hsT[la_k + 2][la_b] = va.z; hsT[la_k + 3][la_b] = va.w;
        *(float4*)(&Wsm[lb_k][lb_n]) = vb0;
        *(float4*)(&Wsm[lb_k + 8][lb_n]) = vb1;
        __syncthreads();
#pragma unroll
        for (int k = 0; k < 16; ++k) {
            float a[4];
            *(float4*)a = *(const float4*)(&hsT[k][b0]);
            ulonglong2 b01 = *(const ulonglong2*)(&Wsm[k][n0]);
            ulonglong2 b23 = *(const ulonglong2*)(&Wsm[k][n0 + 4]);
            unsigned long long bb0 = b01.x, bb1 = b01.y, bb2 = b23.x, bb3 = b23.y;
#pragma unroll
            for (int i = 0; i < 4; ++i) {
                unsigned long long a2 = pack2(a[i]);
                fma2(acc[i][0], a2, bb0);
                fma2(acc[i][1], a2, bb1);
                fma2(acc[i][2], a2, bb2);
                fma2(acc[i][3], a2, bb3);
            }
        }
        __syncthreads();
    }
#pragma unroll
    for (int i = 0; i < 4; ++i) {
#pragma unroll
        for (int j = 0; j < 4; ++j) {
            float2 v = unpack2(acc[i][j]);
            int gn = nblk * 128 + n0 + j * 2;
            *(float2*)(g_part + ((size_t)(kc * Bx + b0 + i)) * G4x + gn) = v;
        }
    }
}

// ---------------- 5. backward (constant-hT) scan --------------------------------
__global__ void bscan_kernel(const float* __restrict__ bh) {
    int idx = blockIdx.x * 256 + threadIdx.x;  // < 49152
    int b = idx / Hx;
    int j = idx - b * Hx;
    float hw[4];
#pragma unroll
    for (int gi = 0; gi < 4; ++gi) {
        int col = j + gi * Hx;
        float v = bh[col];
#pragma unroll
        for (int kc = 0; kc < 6; ++kc)
            v += g_part[((size_t)(kc * Bx + b)) * G4x + col];
        hw[gi] = v;
    }
    float c2 = 0.f;
#pragma unroll 2
    for (int s = Sx - 1; s >= 0; --s) {
        const float* gbp = g_gb + ((size_t)s * Bx + b) * G4x + j;
        float r = sigm(__ldcs(gbp) + hw[0]);
        float f = sigm(__ldcs(gbp + Hx) + hw[1]);
        float gg = tanhf(__ldcs(gbp + 2 * Hx) + hw[2]);
        float o = sigm(__ldcs(gbp + 3 * Hx) + hw[3]);
        c2 = f * c2 + r * gg;
        g_hsb[(size_t)s * (Bx * Hx) + idx] = o * tanhf(c2);
    }
}

// ---------------- 6. output GEMM + pad bias -------------------------------------
__global__ __launch_bounds__(256, 2)
void out_kernel(const float* __restrict__ Wout, const float* __restrict__ bout,
                const int* __restrict__ tokens, float* __restrict__ out) {
    __shared__ float As[64][65];
    __shared__ float Wsm[64][33];
    const int t = threadIdx.x;
    const int rb = blockIdx.x;  // 512 (row blocks of 64)
    const int l = t & 31;
    const int rg = t >> 5;  // 0..7
    float acc[8];
#pragma unroll
    for (int i = 0; i < 8; ++i) acc[i] = 0.f;

    for (int kt = 0; kt < 24; ++kt) {
        int k0 = kt * 64;
        const float* src_base = (k0 < Hx) ? g_hsf : g_hsb;
        int koff = (k0 < Hx) ? k0 : (k0 - Hx);
#pragma unroll
        for (int q = 0; q < 4; ++q) {
            int i = t + 256 * q;
            int row = i >> 4;
            int kq = (i & 15) * 4;
            const float* src =
                src_base + ((size_t)(rb * 64 + row)) * Hx + koff + kq;
            float4 v = *(const float4*)src;
            As[row][kq] = v.x; As[row][kq + 1] = v.y;
            As[row][kq + 2] = v.z; As[row][kq + 3] = v.w;
        }
#pragma unroll
        for (int q = 0; q < 2; ++q) {
            int i = t + 256 * q;
            int k = i >> 3;
            int lq = (i & 7) * 4;
            float4 v = *(const float4*)(Wout + (size_t)(k0 + k) * 32 + lq);
            Wsm[k][lq] = v.x; Wsm[k][lq + 1] = v.y;
            Wsm[k][lq + 2] = v.z; Wsm[k][lq + 3] = v.w;
        }
        __syncthreads();
#pragma unroll 8
        for (int k = 0; k < 64; ++k) {
            float w = Wsm[k][l];
#pragma unroll
            for (int i = 0; i < 8; ++i) acc[i] += As[rg * 8 + i][k] * w;
        }
        __syncthreads();
    }
#pragma unroll
    for (int i = 0; i < 8; ++i) {
        int row = rb * 64 + rg * 8 + i;
        float v = acc[i] + bout[l];
        if (l == 0 && tokens[row] == 1) v += 10000.0f;
        out[(size_t)row * 32 + l] = v;
    }
}

// ---------------- launch ---------------------------------------------------------
extern "C" void kernel_launch(void* const* d_in, const int* in_sizes, int n_in,
                              void* d_out, int out_size) {
    (void)in_sizes; (void)n_in; (void)out_size;
    const int* tokens = (const int*)d_in[0];
    // d_in[1] = tags (unused by forward)
    const float* embedding = (const float*)d_in[2];
    const float* Wi_f = (const float*)d_in[3];
    const float* bi_f = (const float*)d_in[4];
    const float* Wh_f = (const float*)d_in[5];
    const float* bh_f = (const float*)d_in[6];
    const float* Wi_b = (const float*)d_in[7];
    const float* bi_b = (const float*)d_in[8];
    const float* Wh_b = (const float*)d_in[9];
    const float* bh_b = (const float*)d_in[10];
    const float* Wout = (const float*)d_in[11];
    const float* bout = (const float*)d_in[12];
    float* out = (float*)d_out;

    const int fwd_smem = (128 * WS_STRIDE + 128 * HT_STRIDE) * sizeof(float);
    cudaFuncSetAttribute(fwd_persistent,
                         cudaFuncAttributeMaxDynamicSharedMemorySize, fwd_smem);

    // 1. gather embeddings
    embed_kernel<<<SBx * (Ex / 4) / 256, 256>>>(tokens, embedding);
    // 2. input projections (both directions)
    big_gemm_kernel<<<dim3(256, 24), 256>>>(Wi_f, bi_f, 0);  // -> g_xf
    big_gemm_kernel<<<dim3(256, 24), 256>>>(Wi_b, bi_b, 1);  // -> g_gb
    // 3. forward LSTM recurrence (single persistent kernel, 1024 grid syncs)
    fwd_persistent<<<NCTA, 256, fwd_smem>>>(Wh_f, bh_f);
    // 4. hT @ Wh_b partials
    step_gemm_kernel<<<dim3(24, 6), 256>>>(Wh_b);
    // 5. backward scan
    bscan_kernel<<<192, 256>>>(bh_b);
    // 6. output projection + pad bias
    out_kernel<<<512, 256>>>(Wout, bout, tokens, out);
}